// round 17
// baseline (speedup 1.0000x reference)
#include <cuda_runtime.h>
#include <cuda_fp16.h>
#include <math.h>
#include <stdint.h>

// ---------------- constants ----------------
#define BATCH   128
#define DIM     384
#define RES     14
#define NPIX    196
#define KEY_DIM 32
#define NHEADS  12
#define NH_KD   384
#define DH      1536
#define HQKV    2304
#define BN_EPS  1e-5f
#define NPAD    224     // NPIX padded to mult of 32

// ---------------- scratch ----------------
__device__ float g_qkv [ (size_t)BATCH * 768 * NPIX ];            // q+k fp32 only

__device__ __half g_qw_h[ HQKV * DIM ],  g_qw_l[ HQKV * DIM ];
__device__ __half g_pw_h[ DIM * DH ];
__device__ __half g_xT_h[ (size_t)BATCH * NPIX * DIM ],  g_xT_l[ (size_t)BATCH * NPIX * DIM ];
__device__ __half g_v_h [ (size_t)BATCH * DH * NPAD ];              // hi plane only
__device__ __half g_p_h [ (size_t)BATCH * NHEADS * NPIX * NPAD ];   // hi plane only
__device__ __half g_at_h[ (size_t)BATCH * NPIX * DH ];              // hi plane only

// ---------------- helpers ----------------
__device__ __forceinline__ uint32_t smem_u32(const void* p) {
    uint32_t a;
    asm("{ .reg .u64 t; cvta.to.shared.u64 t, %1; cvt.u32.u64 %0, t; }"
        : "=r"(a) : "l"(p));
    return a;
}
#define LDSM4(r, addr) \
    asm volatile("ldmatrix.sync.aligned.m8n8.x4.shared.b16 {%0,%1,%2,%3}, [%4];" \
        : "=r"((r)[0]), "=r"((r)[1]), "=r"((r)[2]), "=r"((r)[3]) : "r"(addr))
#define MMA_F16(d, a, bb) \
    asm volatile("mma.sync.aligned.m16n8k16.row.col.f32.f16.f16.f32 " \
        "{%0,%1,%2,%3}, {%4,%5,%6,%7}, {%8,%9}, {%0,%1,%2,%3};" \
        : "+f"((d)[0]), "+f"((d)[1]), "+f"((d)[2]), "+f"((d)[3]) \
        : "r"((a)[0]), "r"((a)[1]), "r"((a)[2]), "r"((a)[3]), \
          "r"((bb)[0]), "r"((bb)[1]))
#define CP_ASYNC16(dst, src, sz) \
    asm volatile("cp.async.cg.shared.global [%0], [%1], 16, %2;" \
                 :: "r"(dst), "l"(src), "r"(sz))
#define CP_COMMIT() asm volatile("cp.async.commit_group;" ::: "memory")
#define CP_WAIT(n)  asm volatile("cp.async.wait_group %0;" :: "n"(n) : "memory")

__device__ __forceinline__ void split_f16(float v, __half& h, __half& l) {
    h = __float2half_rn(v);
    l = __float2half_rn(v - __half2float(h));
}

// ================= multistage fp16-plane GEMM (unchanged) ====================
template<int OUTMODE, bool HASBN, bool RELU, int TERMS>
__global__ void __launch_bounds__(256, 2)
gemm_f16(const __half* __restrict__ Ah, const __half* __restrict__ Al,
         const __half* __restrict__ Bh, const __half* __restrict__ Bl,
         float* __restrict__ Cf, __half* __restrict__ Ch,
         int nchunks, int lda, int ldb,
         long aOuter, long aInner, int innerCnt,
         long bStride, long cfStride, long cpStride,
         int ldcF, int ldcP, int nrowsB,
         const float* __restrict__ bng, const float* __restrict__ bnb,
         const float* __restrict__ bnm, const float* __restrict__ bnv)
{
    constexpr int KSTEPS = (TERMS == 1) ? 2 : 1;
    constexpr int KPA = 40;
    constexpr int KPB = 40;
    constexpr uint32_t A_BYTES = 128 * KPA * 2;
    constexpr uint32_t B_BYTES = 128 * KPB * 2;
    constexpr uint32_t STAGE   = A_BYTES + B_BYTES;
    constexpr int NSTAGE = 2;
    __shared__ __align__(16) __half smbuf[(NSTAGE * STAGE) / 2];

    const int tid  = threadIdx.x;
    const int wid  = tid >> 5;
    const int lane = tid & 31;
    const int warp_m = wid & 3;
    const int warp_n = wid >> 2;
    const int n0 = blockIdx.x * 128;
    const int m0 = blockIdx.y * 128;
    const int z  = blockIdx.z;
    const int zb = z / innerCnt, zi = z - zb * innerCnt;

    const __half* Agh = Ah + (size_t)zb * aOuter + (size_t)zi * aInner + (size_t)m0 * lda;
    const __half* Agl = (TERMS >= 2) ? (Al + (size_t)zb * aOuter + (size_t)zi * aInner + (size_t)m0 * lda) : nullptr;
    const __half* Bgh = Bh + (size_t)z * bStride;
    const __half* Bgl = (TERMS == 3) ? (Bl + (size_t)z * bStride) : nullptr;

    const uint32_t smb = smem_u32(smbuf);

    const bool full = (n0 + warp_n * 64 + 64) <= nrowsB;
    int jlim = nrowsB - (n0 + warp_n * 64);
    jlim = jlim <= 0 ? 0 : ((jlim + 7) >> 3);
    if (jlim > 8) jlim = 8;

    auto stage = [&](int ch, int s) {
        const int k0 = ch * 16 * KSTEPS;
        const uint32_t sb = smb + (uint32_t)s * STAGE;
#pragma unroll
        for (int i = 0; i < 2; i++) {
            int idx = i * 256 + tid;
            int row = idx >> 2;
            int p   = idx & 3;
            const __half* src;
            if (TERMS >= 2)
                src = (p < 2 ? Agh : Agl) + (size_t)row * lda + k0 + (p & 1) * 8;
            else
                src = Agh + (size_t)row * lda + k0 + p * 8;
            uint32_t dst = sb + (uint32_t)(row * KPA + p * 8) * 2;
            CP_ASYNC16(dst, src, 16u);
        }
        if (TERMS == 3) {
#pragma unroll
            for (int i = 0; i < 2; i++) {
                int idx = i * 256 + tid;
                int row = idx >> 2;
                int p   = idx & 3;
                int rowg = n0 + row;
                unsigned sz = 16u;
                if (rowg >= nrowsB) { rowg = 0; sz = 0u; }
                const __half* src = (p < 2 ? Bgh : Bgl) + (size_t)rowg * ldb + k0 + (p & 1) * 8;
                uint32_t dst = sb + A_BYTES + (uint32_t)(row * KPB + p * 8) * 2;
                CP_ASYNC16(dst, src, sz);
            }
        } else {
#pragma unroll
            for (int i = 0; i < 2; i++) {
                int idx = i * 256 + tid;
                int row = idx >> 2;
                int p   = idx & 3;
                int rowg = n0 + row;
                unsigned sz = 16u;
                if (rowg >= nrowsB) { rowg = 0; sz = 0u; }
                const __half* src = Bgh + (size_t)rowg * ldb + k0 + p * 8;
                uint32_t dst = sb + A_BYTES + (uint32_t)(row * KPB + p * 8) * 2;
                CP_ASYNC16(dst, src, sz);
            }
        }
        CP_COMMIT();
    };

    float acc[2][8][4];
#pragma unroll
    for (int t = 0; t < 2; t++)
#pragma unroll
        for (int j = 0; j < 8; j++)
#pragma unroll
            for (int c = 0; c < 4; c++) acc[t][j][c] = 0.f;

    stage(0, 0);

    for (int ch = 0; ch < nchunks; ch++) {
        CP_WAIT(0);
        __syncthreads();

        {
            int nx = ch + 1;
            if (nx < nchunks) stage(nx, nx & 1);
            else CP_COMMIT();
        }

        const uint32_t base  = smb + (uint32_t)(ch & 1) * STAGE;
        const uint32_t aBase = base;
        const uint32_t bBase = base + A_BYTES;

#pragma unroll
        for (int ks = 0; ks < KSTEPS; ks++) {
            const int kel = ks * 16;
            uint32_t a_hi[2][4], a_lo[2][4];
#pragma unroll
            for (int t = 0; t < 2; t++) {
                int row = warp_m * 32 + t * 16 + (lane & 15);
                int col = kel + ((lane >> 4) << 3);
                uint32_t off = (uint32_t)(row * KPA + col) * 2;
                LDSM4(a_hi[t], aBase + off);
                if (TERMS >= 2) LDSM4(a_lo[t], aBase + off + 32);
            }
            int nrow = warp_n * 64 + (lane & 7) + ((lane >> 4) << 3);
            int bcol = kel + (((lane >> 3) & 1) << 3);
            uint32_t boff = (uint32_t)(nrow * KPB + bcol) * 2;

            if (full) {
                uint32_t b[8][2];
#pragma unroll
                for (int j = 0; j < 4; j++) {
                    uint32_t r[4];
                    LDSM4(r, bBase + boff + (uint32_t)(j * 16 * KPB) * 2);
                    b[2 * j][0] = r[0]; b[2 * j][1] = r[1];
                    b[2 * j + 1][0] = r[2]; b[2 * j + 1][1] = r[3];
                }
#pragma unroll
                for (int t = 0; t < 2; t++)
#pragma unroll
                    for (int j = 0; j < 8; j++) MMA_F16(acc[t][j], a_hi[t], b[j]);
                if (TERMS >= 2) {
#pragma unroll
                    for (int t = 0; t < 2; t++)
#pragma unroll
                        for (int j = 0; j < 8; j++) MMA_F16(acc[t][j], a_lo[t], b[j]);
                }
                if (TERMS == 3) {
#pragma unroll
                    for (int j = 0; j < 4; j++) {
                        uint32_t r[4];
                        LDSM4(r, bBase + boff + 32 + (uint32_t)(j * 16 * KPB) * 2);
                        b[2 * j][0] = r[0]; b[2 * j][1] = r[1];
                        b[2 * j + 1][0] = r[2]; b[2 * j + 1][1] = r[3];
                    }
#pragma unroll
                    for (int t = 0; t < 2; t++)
#pragma unroll
                        for (int j = 0; j < 8; j++) MMA_F16(acc[t][j], a_hi[t], b[j]);
                }
            } else if (jlim > 0) {
                uint32_t b2[2][2];
                {
                    uint32_t r[4];
                    LDSM4(r, bBase + boff);
                    b2[0][0] = r[0]; b2[0][1] = r[1];
                    b2[1][0] = r[2]; b2[1][1] = r[3];
                }
#pragma unroll
                for (int t = 0; t < 2; t++)
#pragma unroll
                    for (int j = 0; j < 2; j++)
                        if (j < jlim) MMA_F16(acc[t][j], a_hi[t], b2[j]);
                if (TERMS >= 2) {
#pragma unroll
                    for (int t = 0; t < 2; t++)
#pragma unroll
                        for (int j = 0; j < 2; j++)
                            if (j < jlim) MMA_F16(acc[t][j], a_lo[t], b2[j]);
                }
                if (TERMS == 3) {
                    uint32_t r[4];
                    LDSM4(r, bBase + boff + 32);
                    b2[0][0] = r[0]; b2[0][1] = r[1];
                    b2[1][0] = r[2]; b2[1][1] = r[3];
#pragma unroll
                    for (int t = 0; t < 2; t++)
#pragma unroll
                        for (int j = 0; j < 2; j++)
                            if (j < jlim) MMA_F16(acc[t][j], a_hi[t], b2[j]);
                }
            }
        }
    }

    // ---------------- epilogues ----------------
    if (OUTMODE == 0 || OUTMODE == 3) {
#pragma unroll
        for (int t = 0; t < 2; t++) {
            int r0 = m0 + warp_m * 32 + t * 16 + (lane >> 2);
            int r1 = r0 + 8;
            float s0 = 1.f, h0 = 0.f, s1 = 1.f, h1 = 0.f;
            if (HASBN) {
                float a = bng[r0] * rsqrtf(bnv[r0] + BN_EPS);
                s0 = a; h0 = bnb[r0] - bnm[r0] * a;
                float c = bng[r1] * rsqrtf(bnv[r1] + BN_EPS);
                s1 = c; h1 = bnb[r1] - bnm[r1] * c;
            }
#pragma unroll
            for (int j = 0; j < 8; j++) {
                int nn = n0 + warp_n * 64 + j * 8 + 2 * (lane & 3);
                float v0 = acc[t][j][0] * s0 + h0;
                float v1 = acc[t][j][1] * s0 + h0;
                float v2 = acc[t][j][2] * s1 + h1;
                float v3 = acc[t][j][3] * s1 + h1;
                if (RELU) {
                    v0 = fmaxf(v0, 0.f); v1 = fmaxf(v1, 0.f);
                    v2 = fmaxf(v2, 0.f); v3 = fmaxf(v3, 0.f);
                }
                if (OUTMODE == 0) {
                    if (nn < NPIX) {
                        *(float2*)(Cf + (size_t)z * cfStride + (size_t)r0 * ldcF + nn) = make_float2(v0, v1);
                        *(float2*)(Cf + (size_t)z * cfStride + (size_t)r1 * ldcF + nn) = make_float2(v2, v3);
                    }
                } else {
                    if (nn < NPAD) {
                        if (nn >= NPIX) { v0 = v1 = v2 = v3 = 0.f; }
                        size_t p0 = (size_t)z * cpStride + (size_t)r0 * ldcP + nn;
                        size_t p1 = (size_t)z * cpStride + (size_t)r1 * ldcP + nn;
                        *(__half2*)(Ch + p0) = __half2(__float2half_rn(v0), __float2half_rn(v1));
                        *(__half2*)(Ch + p1) = __half2(__float2half_rn(v2), __float2half_rn(v3));
                    }
                }
            }
        }
    } else {
        __half* ep = smbuf;   // [128 i][136 d]
        __syncthreads();
#pragma unroll
        for (int t = 0; t < 2; t++) {
            int d0 = warp_m * 32 + t * 16 + (lane >> 2);
            int d1 = d0 + 8;
#pragma unroll
            for (int j = 0; j < 8; j++) {
                int il = warp_n * 64 + j * 8 + 2 * (lane & 3);
                float v0 = acc[t][j][0], v1 = acc[t][j][1];
                float v2 = acc[t][j][2], v3 = acc[t][j][3];
                if (RELU) {
                    v0 = fmaxf(v0, 0.f); v1 = fmaxf(v1, 0.f);
                    v2 = fmaxf(v2, 0.f); v3 = fmaxf(v3, 0.f);
                }
                ep[il * 136 + d0]       = __float2half_rn(v0);
                ep[(il + 1) * 136 + d0] = __float2half_rn(v1);
                ep[il * 136 + d1]       = __float2half_rn(v2);
                ep[(il + 1) * 136 + d1] = __float2half_rn(v3);
            }
        }
        __syncthreads();
        __half* dst = Ch + (size_t)zb * cpStride + (size_t)zi * 128;
        for (int c2 = tid; c2 < 2048; c2 += 256) {
            int row = c2 >> 4, off = (c2 & 15) * 8;
            int i = n0 + row;
            if (i < NPIX) {
                uint4 val = *(uint4*)(ep + row * 136 + off);
                *(uint4*)(dst + (size_t)i * ldcP + off) = val;
            }
        }
    }
}

// ---------------- pre-convert kernels ----------------
__global__ void convert_weights(const float* __restrict__ qw, const float* __restrict__ pw)
{
    int i = blockIdx.x * 256 + threadIdx.x;
    if (i < HQKV * DIM) split_f16(qw[i], g_qw_h[i], g_qw_l[i]);
    if (i < DIM * DH)   g_pw_h[i] = __float2half_rn(pw[i]);
}

// transpose x: [B, DIM, NPIX] -> xT hi/lo [B, NPIX, DIM], half2 stores.
__global__ void transpose_x(const float* __restrict__ x)
{
    __shared__ float t[64][33];
    int p0 = blockIdx.x * 32, c0 = blockIdx.y * 64, b = blockIdx.z;
    int tx = threadIdx.x, ty = threadIdx.y;
    for (int r = ty; r < 64; r += 8) {
        int p = p0 + tx;
        t[r][tx] = (p < NPIX) ? x[((size_t)b * DIM + c0 + r) * NPIX + p] : 0.f;
    }
    __syncthreads();
    for (int r = ty; r < 32; r += 8) {
        int p = p0 + r;
        if (p < NPIX) {
            float v0 = t[2 * tx][r], v1 = t[2 * tx + 1][r];
            __half h0, l0, h1, l1;
            split_f16(v0, h0, l0);
            split_f16(v1, h1, l1);
            size_t o = ((size_t)b * NPIX + p) * DIM + c0 + 2 * tx;
            *(__half2*)(g_xT_h + o) = __half2(h0, h1);
            *(__half2*)(g_xT_l + o) = __half2(l0, l1);
        }
    }
}

// ---------------- softmax (fused dwconv+BN + bias, row-split x2) ------------
__global__ void attn_softmax(const float* __restrict__ ab, const int* __restrict__ idxs,
                             const float* __restrict__ dww,
                             const float* __restrict__ dwg, const float* __restrict__ dwb,
                             const float* __restrict__ dwm, const float* __restrict__ dwv)
{
    const int h  = blockIdx.x;
    const int b  = blockIdx.y;
    const int zi = blockIdx.z;          // 0 or 1: rows [98*zi, 98*zi+98)
    __shared__ float k_s[32 * 224];     // reused: first q_raw, then K
    __shared__ float q_s[32 * 99];      // dwconv+BN output, this CTA's 98 i-rows
    __shared__ float ab_s[NPIX];
    __shared__ float wgt_s[32 * 9];
    __shared__ float bn_s[32][2];

    const int tid  = threadIdx.x;
    const int ibase = 98 * zi;
    const int iend  = ibase + 98;

    const float* qraw = g_qkv + (size_t)b * 768 * NPIX + (size_t)h * KEY_DIM * NPIX;
    const float* kg   = g_qkv + (size_t)b * 768 * NPIX + (size_t)(NH_KD + h * KEY_DIM) * NPIX;

    // phase 1: stage raw q plane [32][196] into k_s
    for (int idx = tid; idx < 32 * 224; idx += 256) {
        int d = idx / 224, j = idx % 224;
        k_s[idx] = (j < NPIX) ? qraw[d * NPIX + j] : 0.f;
    }
    for (int idx = tid; idx < 32 * 9; idx += 256)
        wgt_s[idx] = dww[(h * KEY_DIM + idx / 9) * 9 + idx % 9];
    if (tid < 32) {
        int c = h * KEY_DIM + tid;
        float s = dwg[c] * rsqrtf(dwv[c] + BN_EPS);
        bn_s[tid][0] = s;
        bn_s[tid][1] = dwb[c] - dwm[c] * s;
    }
    if (tid < NPIX) ab_s[tid] = ab[h * NPIX + tid];
    __syncthreads();

    // phase 2: dwconv 3x3 + BN -> q_s[d][il]   (il = i - ibase)
    for (int e = tid; e < 32 * 98; e += 256) {
        int d  = e / 98;
        int il = e - d * 98;
        int p  = ibase + il;
        int y = p / RES, x = p - y * RES;
        float acc = 0.f;
#pragma unroll
        for (int ky = 0; ky < 3; ky++) {
            int yy = y + ky - 1;
            if (yy < 0 || yy >= RES) continue;
#pragma unroll
            for (int kx = 0; kx < 3; kx++) {
                int xx = x + kx - 1;
                if (xx < 0 || xx >= RES) continue;
                acc += k_s[d * 224 + yy * RES + xx] * wgt_s[d * 9 + ky * 3 + kx];
            }
        }
        q_s[d * 99 + il] = acc * bn_s[d][0] + bn_s[d][1];
    }
    __syncthreads();

    // phase 3: overwrite k_s with K plane
    for (int idx = tid; idx < 32 * 224; idx += 256) {
        int d = idx / 224, j = idx % 224;
        k_s[idx] = (j < NPIX) ? kg[d * NPIX + j] : 0.f;
    }
    __syncthreads();

    const int w    = tid >> 5;
    const int lane = tid & 31;
    const size_t zoff = ((size_t)b * NHEADS + h) * NPIX * NPAD;
    const float scale = 0.17677669529663687f;

    for (int i0 = ibase + w * 4; i0 < iend; i0 += 32) {
        float q_reg[4];
#pragma unroll
        for (int r = 0; r < 4; r++) {
            int i = i0 + r;
            q_reg[r] = (i < iend) ? q_s[lane * 99 + (i - ibase)] : 0.f;
        }

        float s[4][7];
#pragma unroll
        for (int r = 0; r < 4; r++)
#pragma unroll
            for (int m = 0; m < 7; m++) s[r][m] = 0.f;

        for (int d = 0; d < 32; d++) {
            float qv[4];
#pragma unroll
            for (int r = 0; r < 4; r++)
                qv[r] = __shfl_sync(0xffffffffu, q_reg[r], d);
#pragma unroll
            for (int m = 0; m < 7; m++) {
                float kv = k_s[d * 224 + lane + m * 32];
#pragma unroll
                for (int r = 0; r < 4; r++) s[r][m] += qv[r] * kv;
            }
        }

#pragma unroll
        for (int r = 0; r < 4; r++) {
            int i = i0 + r;
            if (i >= iend) break;
            float sv[7];
            float mx = -1e30f;
#pragma unroll
            for (int m = 0; m < 7; m++) {
                int j = lane + m * 32;
                float val;
                if (j < NPIX) {
                    int bi = idxs[(size_t)i * NPIX + j];
                    val = s[r][m] * scale + ab_s[bi];
                } else val = -1e30f;
                sv[m] = val;
                mx = fmaxf(mx, val);
            }
#pragma unroll
            for (int off = 16; off; off >>= 1)
                mx = fmaxf(mx, __shfl_xor_sync(0xffffffffu, mx, off));
            float sum = 0.f;
#pragma unroll
            for (int m = 0; m < 7; m++) {
                sv[m] = __expf(sv[m] - mx);
                sum += sv[m];
            }
#pragma unroll
            for (int off = 16; off; off >>= 1)
                sum += __shfl_xor_sync(0xffffffffu, sum, off);
            float inv = 1.f / sum;
#pragma unroll
            for (int m = 0; m < 7; m++) {
                int j = lane + m * 32;
                if (j < NPIX) {
                    g_p_h[zoff + (size_t)i * NPAD + j] = __float2half_rn(sv[m] * inv);
                } else if (j < NPAD) {
                    g_p_h[zoff + (size_t)i * NPAD + j] = __float2half_rn(0.f);
                }
            }
        }
    }
}

// ---------------- launch ----------------------------------------------------
extern "C" void kernel_launch(void* const* d_in, const int* in_sizes, int n_in,
                              void* d_out, int out_size)
{
    const float* x      = (const float*)d_in[0];
    const float* qkv_w  = (const float*)d_in[1];
    const float* qkv_g  = (const float*)d_in[2];
    const float* qkv_b  = (const float*)d_in[3];
    const float* qkv_m  = (const float*)d_in[4];
    const float* qkv_v  = (const float*)d_in[5];
    const float* dw_w   = (const float*)d_in[6];
    const float* dw_g   = (const float*)d_in[7];
    const float* dw_b   = (const float*)d_in[8];
    const float* dw_m   = (const float*)d_in[9];
    const float* dw_v   = (const float*)d_in[10];
    const float* proj_w = (const float*)d_in[11];
    const float* proj_g = (const float*)d_in[12];
    const float* proj_b = (const float*)d_in[13];
    const float* proj_m = (const float*)d_in[14];
    const float* proj_v = (const float*)d_in[15];
    const float* ab     = (const float*)d_in[16];
    const int*   bidx   = (const int*)d_in[17];
    float* out = (float*)d_out;

    float* qkvf;  cudaGetSymbolAddress((void**)&qkvf,  g_qkv);
    __half *qwh, *qwl, *pwh, *xth, *xtl, *vh, *ph, *ath;
    cudaGetSymbolAddress((void**)&qwh, g_qw_h);  cudaGetSymbolAddress((void**)&qwl, g_qw_l);
    cudaGetSymbolAddress((void**)&pwh, g_pw_h);
    cudaGetSymbolAddress((void**)&xth, g_xT_h);  cudaGetSymbolAddress((void**)&xtl, g_xT_l);
    cudaGetSymbolAddress((void**)&vh,  g_v_h);
    cudaGetSymbolAddress((void**)&ph,  g_p_h);
    cudaGetSymbolAddress((void**)&ath, g_at_h);

    // P0: convert weights + transpose/convert x
    convert_weights<<<(HQKV * DIM + 255) / 256, 256>>>(qkv_w, proj_w);
    transpose_x<<<dim3(7, 6, BATCH), dim3(32, 8)>>>(x);

    // K1a: q,k rows = BN(W_qkv[0:768] @ x)  3-term -> fp32   (K-chunk 16)
    gemm_f16<0, true, false, 3><<<dim3(2, 768 / 128, BATCH), 256>>>(
        qwh, qwl, xth, xtl,
        qkvf, nullptr,
        DIM / 16, DIM, DIM,
        0L, 0L, 1,
        (long)NPIX * DIM, (long)768 * NPIX, 0L,
        NPIX, 0, NPIX,
        qkv_g, qkv_b, qkv_m, qkv_v);

    // K1b: V rows = BN(W_qkv_hi @ x_hi)  1-term -> fp16 hi   (K-chunk 32)
    gemm_f16<3, true, false, 1><<<dim3(2, DH / 128, BATCH), 256>>>(
        qwh + (size_t)768 * DIM, nullptr, xth, nullptr,
        nullptr, vh,
        DIM / 32, DIM, DIM,
        0L, 0L, 1,
        (long)NPIX * DIM, 0L, (long)DH * NPAD,
        0, NPAD, NPIX,
        qkv_g + 768, qkv_b + 768, qkv_m + 768, qkv_v + 768);

    // K4: softmax (fused dwconv+BN + bias, 2-way row split) -> P hi plane
    attn_softmax<<<dim3(NHEADS, BATCH, 2), 256>>>(ab, bidx, dw_w, dw_g, dw_b, dw_m, dw_v);

    // K5: attT hi = relu(V_hi @ P^T)^T  1-term  (K-chunk 32)
    gemm_f16<2, false, true, 1><<<dim3(2, 1, BATCH * NHEADS), 256>>>(
        vh, nullptr, ph, nullptr,
        nullptr, ath,
        NPAD / 32, NPAD, NPAD,
        (long)DH * NPAD, (long)128 * NPAD, NHEADS,
        (long)NPIX * NPAD, 0L, (long)NPIX * DH,
        0, DH, NPIX,
        nullptr, nullptr, nullptr, nullptr);

    // K6: out = BN(W_proj_hi @ att)  1-term  (K-chunk 32)
    gemm_f16<0, true, false, 1><<<dim3(2, DIM / 128, BATCH), 256>>>(
        pwh, nullptr, ath, nullptr,
        out, nullptr,
        DH / 32, DH, DH,
        0L, 0L, 1,
        (long)NPIX * DH, (long)DIM * NPIX, 0L,
        NPIX, 0, NPIX,
        proj_g, proj_b, proj_m, proj_v);
}